// round 4
// baseline (speedup 1.0000x reference)
#include <cuda_runtime.h>
#include <cstdint>

// Static problem shape (fixed by setup_inputs).
#define NUM_B   128
#define NPG     128
#define BNN     (NUM_B * NPG * NPG)   // 2,097,152 output rows
#define DFEAT   64
#define E_MAX   524288

// ---------------------------------------------------------------------------
// Scratch (allocation-free rule: __device__ globals).
// g_count[slot]  : number of original edges landing on this slot
// g_edge[slot]   : first edge id for the slot (valid iff g_count > 0)
// g_dup / g_dupcnt : overflow list of duplicate edges (2nd, 3rd, ... per slot)
// ---------------------------------------------------------------------------
__device__ unsigned g_count[BNN];
__device__ unsigned g_edge[BNN];
__device__ unsigned g_dup[E_MAX];
__device__ unsigned g_dupcnt;

// ---------------------------------------------------------------------------
// Kernel 0: reset scratch (counts + dup counter). 8.4 MB, ~2us.
// Grid: BNN/4 threads, uint4 stores. 2048 blocks x 256, exact.
// ---------------------------------------------------------------------------
__global__ void zero_scratch_kernel() {
    unsigned t = blockIdx.x * blockDim.x + threadIdx.x;
    reinterpret_cast<uint4*>(g_count)[t] = make_uint4(0, 0, 0, 0);
    if (t == 0) g_dupcnt = 0;
}

// ---------------------------------------------------------------------------
// Kernel 1: out_idx prefix (float32).
//   out[i]       = i >> 7
//   out[BNN + j] = ((j >> 14) << 7) + (j & 127)
// ---------------------------------------------------------------------------
__global__ void fill_idx_kernel(float* __restrict__ out) {
    int i4 = blockIdx.x * blockDim.x + threadIdx.x;
    int i = i4 << 2;
    float4 v;
    if (i < BNN) {
        float r = (float)(i >> 7);
        v = make_float4(r, r, r, r);
    } else {
        int j = i - BNN;
        int base = ((j >> 14) << 7) + (j & 127);
        v = make_float4((float)(base + 0), (float)(base + 1),
                        (float)(base + 2), (float)(base + 3));
    }
    reinterpret_cast<float4*>(out)[i4] = v;
}

// ---------------------------------------------------------------------------
// Kernel 2: counting pre-pass. One thread per edge. Count array is 8.4 MB
// => all atomics hit L2. First edge per slot is recorded; later ones go to
// the duplicate list.
// ---------------------------------------------------------------------------
__global__ void count_kernel(const int* __restrict__ edge_index,
                             const int* __restrict__ batch, int E) {
    int e = blockIdx.x * blockDim.x + threadIdx.x;
    if (e >= E) return;
    int r = edge_index[e];
    int c = edge_index[E + e];
    int g = batch[r];
    unsigned pos = (unsigned)(r * NPG + c - g * NPG);
    unsigned old = atomicAdd(&g_count[pos], 1u);
    if (old == 0u) {
        g_edge[pos] = (unsigned)e;
    } else {
        unsigned d = atomicAdd(&g_dupcnt, 1u);
        g_dup[d] = (unsigned)e;
    }
}

// ---------------------------------------------------------------------------
// Kernel 3: fused zero + gather-write. 16 consecutive threads own one output
// row (64 floats); each writes one float4 (fully coalesced 256B per group).
// Leader lane of each 16-thread group loads count/edge once, broadcasts via
// shfl. Empty slot -> streaming zero store; occupied -> gather attr row.
// Grid: BNN*16 threads = 131072 blocks x 256, exact (no tail).
// ---------------------------------------------------------------------------
__global__ void write_out_kernel(const float* __restrict__ edge_attr,
                                 float* __restrict__ out_val) {
    unsigned t = blockIdx.x * blockDim.x + threadIdx.x;
    unsigned slot = t >> 4;
    unsigned chunk = t & 15u;
    unsigned lane = threadIdx.x & 31u;

    unsigned cnt = 0u, e = 0u;
    if ((lane & 15u) == 0u) {
        cnt = g_count[slot];
        if (cnt) e = g_edge[slot];
    }
    cnt = __shfl_sync(0xffffffffu, cnt, lane & 0x10u);
    e   = __shfl_sync(0xffffffffu, e,   lane & 0x10u);

    float4 v = make_float4(0.f, 0.f, 0.f, 0.f);
    if (cnt)
        v = __ldcs(reinterpret_cast<const float4*>(edge_attr) +
                   (((size_t)e << 4) + chunk));
    __stcs(reinterpret_cast<float4*>(out_val) + (((size_t)slot << 4) + chunk), v);
}

// ---------------------------------------------------------------------------
// Kernel 4: fold in duplicate edges with vector reductions (~64K edges).
// One thread per duplicate; 16 x red.global.add.v4.f32 per row.
// ---------------------------------------------------------------------------
__global__ void dup_kernel(const int* __restrict__ edge_index,
                           const float* __restrict__ edge_attr,
                           const int* __restrict__ batch,
                           float* __restrict__ out_val, int E) {
    unsigned i = blockIdx.x * blockDim.x + threadIdx.x;
    if (i >= g_dupcnt) return;
    int e = (int)g_dup[i];
    int r = edge_index[e];
    int c = edge_index[E + e];
    int g = batch[r];
    unsigned pos = (unsigned)(r * NPG + c - g * NPG);

    const float4* a = reinterpret_cast<const float4*>(edge_attr) + ((size_t)e << 4);
    float* p = out_val + ((size_t)pos << 6);
#pragma unroll
    for (int k = 0; k < 16; k++) {
        float4 v = __ldg(&a[k]);
        asm volatile("red.global.add.v4.f32 [%0], {%1,%2,%3,%4};"
                     :: "l"(p + 4 * k), "f"(v.x), "f"(v.y), "f"(v.z), "f"(v.w)
                     : "memory");
    }
}

// ---------------------------------------------------------------------------
// Launch. Inputs: [0] edge_index int32 [2E], [1] edge_attr f32 [E*64],
// [2] batch int32 [B*n]. Output: f32 concat [idx (2*BNN), val (BNN*64)].
// ---------------------------------------------------------------------------
extern "C" void kernel_launch(void* const* d_in, const int* in_sizes, int n_in,
                              void* d_out, int out_size) {
    const int*   edge_index = (const int*)d_in[0];
    const float* edge_attr  = (const float*)d_in[1];
    const int*   batch      = (const int*)d_in[2];
    const int E = in_sizes[0] / 2;

    float* out = (float*)d_out;
    const long long idx_count = 2LL * BNN;
    const long long val_count = (long long)BNN * DFEAT;

    long long val_off = 0;
    if ((long long)out_size >= idx_count + val_count) {
        val_off = idx_count;
        fill_idx_kernel<<<(int)(idx_count / 4 / 256), 256>>>(out);
    }
    float* out_val = out + val_off;

    zero_scratch_kernel<<<BNN / 4 / 256, 256>>>();
    count_kernel<<<(E + 255) / 256, 256>>>(edge_index, batch, E);
    write_out_kernel<<<BNN * 16 / 256, 256>>>(edge_attr, out_val);
    dup_kernel<<<(E + 255) / 256, 256>>>(edge_index, edge_attr, batch, out_val, E);
}

// round 5
// speedup vs baseline: 1.2337x; 1.2337x over previous
#include <cuda_runtime.h>
#include <cstdint>

// Static problem shape (fixed by setup_inputs).
#define NUM_B   128
#define NPG     128
#define BNN     (NUM_B * NPG * NPG)   // 2,097,152 output rows
#define DFEAT   64
#define E_MAX   524288

// ---------------------------------------------------------------------------
// Scratch (__device__ globals; allocation-free rule).
// g_meta[slot] : 0 = empty, else (edge_id + 1) of one edge landing here
// g_dup        : all displaced/duplicate edges, folded in atomically at the end
// ---------------------------------------------------------------------------
__device__ unsigned g_meta[BNN];
__device__ unsigned g_dup[E_MAX];
__device__ unsigned g_dupcnt;

// ---------------------------------------------------------------------------
// Kernel 0: reset scratch (4.2 MB of meta + dup counter). ~1us.
// BNN/4 uint4 stores = 524288 threads = 2048 blocks x 256, exact.
// ---------------------------------------------------------------------------
__global__ void zero_scratch_kernel() {
    unsigned t = blockIdx.x * blockDim.x + threadIdx.x;
    reinterpret_cast<uint4*>(g_meta)[t] = make_uint4(0, 0, 0, 0);
    if (t == 0) g_dupcnt = 0;
}

// ---------------------------------------------------------------------------
// Kernel 1: out_idx prefix (float32).
//   out[i]       = i >> 7
//   out[BNN + j] = ((j >> 14) << 7) + (j & 127)
// ---------------------------------------------------------------------------
__global__ void fill_idx_kernel(float* __restrict__ out) {
    int i4 = blockIdx.x * blockDim.x + threadIdx.x;
    int i = i4 << 2;
    float4 v;
    if (i < BNN) {
        float r = (float)(i >> 7);
        v = make_float4(r, r, r, r);
    } else {
        int j = i - BNN;
        int base = ((j >> 14) << 7) + (j & 127);
        v = make_float4((float)(base + 0), (float)(base + 1),
                        (float)(base + 2), (float)(base + 3));
    }
    reinterpret_cast<float4*>(out)[i4] = v;
}

// ---------------------------------------------------------------------------
// Kernel 2: claim pass. One thread per edge. atomicExch claims the slot
// (last writer wins the dedicated write); any displaced previous edge goes
// to the duplicate list. Meta array is 8.4 MB => atomics are L2-resident.
// ---------------------------------------------------------------------------
__global__ void claim_kernel(const int* __restrict__ edge_index,
                             const int* __restrict__ batch, int E) {
    int e = blockIdx.x * blockDim.x + threadIdx.x;
    if (e >= E) return;
    int r = edge_index[e];
    int c = edge_index[E + e];
    int g = batch[r];
    unsigned pos = (unsigned)(r * NPG + c - g * NPG);
    unsigned old = atomicExch(&g_meta[pos], (unsigned)e + 1u);
    if (old != 0u) {
        unsigned d = atomicAdd(&g_dupcnt, 1u);   // uniform addr -> warp-aggregated
        g_dup[d] = old - 1u;
    }
}

// ---------------------------------------------------------------------------
// Kernel 3: fused zero + gather-write, ILP=4.
// chunk index ci in [0, BNN*16): slot = ci>>4, float4-in-row = ci&15.
// Each thread handles 4 chunks spaced by the full thread count, so its
// 4 metadata loads and 4 gathers are independent (MLP=4). All 16 lanes of a
// slot group load the same g_meta word (intra-warp broadcast, no shfl).
// Empty slot -> streaming zero; occupied -> gather attr row. Exact grid.
// ---------------------------------------------------------------------------
#define WO_BLOCKS  32768
#define WO_STRIDE  (WO_BLOCKS * 256u)          // 8,388,608 threads
#define WO_ILP     4                            // 4 * stride = BNN*16 chunks

__global__ void write_out_kernel(const float* __restrict__ edge_attr,
                                 float* __restrict__ out_val) {
    unsigned t = blockIdx.x * 256u + threadIdx.x;

    unsigned meta[WO_ILP];
#pragma unroll
    for (int k = 0; k < WO_ILP; k++) {
        unsigned ci = t + (unsigned)k * WO_STRIDE;
        meta[k] = __ldg(&g_meta[ci >> 4]);
    }

    float4 v[WO_ILP];
#pragma unroll
    for (int k = 0; k < WO_ILP; k++) {
        unsigned ci = t + (unsigned)k * WO_STRIDE;
        v[k] = make_float4(0.f, 0.f, 0.f, 0.f);
        if (meta[k])
            v[k] = __ldcs(reinterpret_cast<const float4*>(edge_attr) +
                          (((size_t)(meta[k] - 1u) << 4) + (ci & 15u)));
    }

#pragma unroll
    for (int k = 0; k < WO_ILP; k++) {
        unsigned ci = t + (unsigned)k * WO_STRIDE;
        __stcs(reinterpret_cast<float4*>(out_val) + ci, v[k]);
    }
}

// ---------------------------------------------------------------------------
// Kernel 4: fold in displaced edges (~60K expected) with vector reductions.
// ---------------------------------------------------------------------------
__global__ void dup_kernel(const int* __restrict__ edge_index,
                           const float* __restrict__ edge_attr,
                           const int* __restrict__ batch,
                           float* __restrict__ out_val, int E) {
    unsigned i = blockIdx.x * blockDim.x + threadIdx.x;
    if (i >= g_dupcnt) return;
    int e = (int)g_dup[i];
    int r = edge_index[e];
    int c = edge_index[E + e];
    int g = batch[r];
    unsigned pos = (unsigned)(r * NPG + c - g * NPG);

    const float4* a = reinterpret_cast<const float4*>(edge_attr) + ((size_t)e << 4);
    float* p = out_val + ((size_t)pos << 6);
#pragma unroll
    for (int k = 0; k < 16; k++) {
        float4 v = __ldg(&a[k]);
        asm volatile("red.global.add.v4.f32 [%0], {%1,%2,%3,%4};"
                     :: "l"(p + 4 * k), "f"(v.x), "f"(v.y), "f"(v.z), "f"(v.w)
                     : "memory");
    }
}

// ---------------------------------------------------------------------------
// Launch. Inputs: [0] edge_index int32 [2E], [1] edge_attr f32 [E*64],
// [2] batch int32 [B*n]. Output: f32 concat [idx (2*BNN), val (BNN*64)].
// ---------------------------------------------------------------------------
extern "C" void kernel_launch(void* const* d_in, const int* in_sizes, int n_in,
                              void* d_out, int out_size) {
    const int*   edge_index = (const int*)d_in[0];
    const float* edge_attr  = (const float*)d_in[1];
    const int*   batch      = (const int*)d_in[2];
    const int E = in_sizes[0] / 2;

    float* out = (float*)d_out;
    const long long idx_count = 2LL * BNN;
    const long long val_count = (long long)BNN * DFEAT;

    long long val_off = 0;
    if ((long long)out_size >= idx_count + val_count) {
        val_off = idx_count;
        fill_idx_kernel<<<(int)(idx_count / 4 / 256), 256>>>(out);
    }
    float* out_val = out + val_off;

    zero_scratch_kernel<<<BNN / 4 / 256, 256>>>();
    claim_kernel<<<(E + 255) / 256, 256>>>(edge_index, batch, E);
    write_out_kernel<<<WO_BLOCKS, 256>>>(edge_attr, out_val);
    dup_kernel<<<(E + 255) / 256, 256>>>(edge_index, edge_attr, batch, out_val, E);
}